// round 8
// baseline (speedup 1.0000x reference)
#include <cuda_runtime.h>
#include <cuda_fp16.h>
#include <math.h>
#include <stdint.h>

#define NROWS 4096
#define NDIM  2048
#define TEMP_INV 2.0f
#define QSCALE 64.0f           // fp8 quantization scale
#define QS2_INV (1.0f / (QSCALE * QSCALE))

// ---------------- device scratch ----------------
__device__ __align__(1024) uint8_t g_A8[NROWS * NDIM];   // e4m3, normalized * 64
__device__ __align__(1024) uint8_t g_C8[NROWS * NDIM];   // e4m3, normalized * 64
__device__ float  g_invB[NROWS];
__device__ float  g_csA[NDIM];
__device__ float  g_csB[NDIM];
__device__ double g_S;
__device__ float  g_pos;

// ---------------- raw-PTX fp8 conversion ----------------
__device__ __forceinline__ uint16_t pack_e4m3x2(float hi, float lo) {
    uint16_t r;
    asm("cvt.rn.satfinite.e4m3x2.f32 %0, %1, %2;" : "=h"(r) : "f"(hi), "f"(lo));
    return r;
}
__device__ __forceinline__ float2 unpack_e4m3x2(uint16_t v) {
    uint32_t h2;
    asm("cvt.rn.f16x2.e4m3x2 %0, %1;" : "=r"(h2) : "h"(v));
    __half2 h = *reinterpret_cast<__half2*>(&h2);
    return __half22float2(h);
}

// ---------------- zero accumulators ----------------
__global__ void zero_kernel() {
    int i = blockIdx.x * blockDim.x + threadIdx.x;
    if (i < NDIM) { g_csA[i] = 0.f; g_csB[i] = 0.f; }
    if (i == 0)   { g_S = 0.0; g_pos = 0.f; }
}

// ---------------- fused norm + normalize -> e4m3 (*64) ----------------
__global__ __launch_bounds__(256) void fuse_norm_kernel(const float* __restrict__ X,
                                                        uint8_t* __restrict__ out) {
    int row = blockIdx.x;
    int tid = threadIdx.x;
    const float4* p = reinterpret_cast<const float4*>(X + (size_t)row * NDIM);
    float4 a = p[tid * 2 + 0];
    float4 b = p[tid * 2 + 1];
    float s = a.x * a.x + a.y * a.y + a.z * a.z + a.w * a.w
            + b.x * b.x + b.y * b.y + b.z * b.z + b.w * b.w;
    for (int off = 16; off; off >>= 1) s += __shfl_xor_sync(0xffffffffu, s, off);
    __shared__ float red[8];
    __shared__ float s_inv;
    if ((tid & 31) == 0) red[tid >> 5] = s;
    __syncthreads();
    if (tid == 0) {
        float t = 0.f;
        #pragma unroll
        for (int w = 0; w < 8; w++) t += red[w];
        s_inv = rsqrtf(t) * QSCALE;
    }
    __syncthreads();
    float inv = s_inv;

    uint16_t q0 = pack_e4m3x2(a.y * inv, a.x * inv);
    uint16_t q1 = pack_e4m3x2(a.w * inv, a.z * inv);
    uint16_t q2 = pack_e4m3x2(b.y * inv, b.x * inv);
    uint16_t q3 = pack_e4m3x2(b.w * inv, b.z * inv);
    uint2 o;
    o.x = (uint32_t)q0 | ((uint32_t)q1 << 16);
    o.y = (uint32_t)q2 | ((uint32_t)q3 << 16);
    reinterpret_cast<uint2*>(out + (size_t)row * NDIM)[tid] = o;
}

// ---------------- per-row inverse L2 norm (B only) ----------------
__global__ void row_norms_kernel(const float* __restrict__ X, float* __restrict__ inv) {
    int row = blockIdx.x;
    const float4* p = reinterpret_cast<const float4*>(X + (size_t)row * NDIM);
    float s = 0.f;
    for (int i = threadIdx.x; i < NDIM / 4; i += blockDim.x) {
        float4 v = p[i];
        s += v.x * v.x + v.y * v.y + v.z * v.z + v.w * v.w;
    }
    for (int off = 16; off; off >>= 1) s += __shfl_xor_sync(0xffffffffu, s, off);
    __shared__ float red[8];
    if ((threadIdx.x & 31) == 0) red[threadIdx.x >> 5] = s;
    __syncthreads();
    if (threadIdx.x == 0) {
        float t = 0.f;
        #pragma unroll
        for (int w = 0; w < 8; w++) t += red[w];
        inv[row] = rsqrtf(t);
    }
}

// ---------------- column sums ----------------
__global__ void colsum_fp8_kernel(const uint8_t* __restrict__ X8,
                                  float* __restrict__ cs) {
    int d2 = blockIdx.x * blockDim.x + threadIdx.x;   // pair index
    int i0 = blockIdx.y * (NROWS / 32);
    float s0 = 0.f, s1 = 0.f;
    #pragma unroll 4
    for (int i = 0; i < NROWS / 32; i++) {
        uint16_t v = *reinterpret_cast<const uint16_t*>(&X8[(size_t)(i0 + i) * NDIM + d2 * 2]);
        float2 f = unpack_e4m3x2(v);
        s0 += f.x; s1 += f.y;
    }
    atomicAdd(&cs[d2 * 2 + 0], s0 * (1.0f / QSCALE));
    atomicAdd(&cs[d2 * 2 + 1], s1 * (1.0f / QSCALE));
}

__global__ void colsum_f32_kernel(const float* __restrict__ X,
                                  const float* __restrict__ inv,
                                  float* __restrict__ cs) {
    int d  = blockIdx.x * blockDim.x + threadIdx.x;
    int i0 = blockIdx.y * (NROWS / 32);
    float s = 0.f;
    #pragma unroll 4
    for (int i = 0; i < NROWS / 32; i++)
        s += X[(size_t)(i0 + i) * NDIM + d] * inv[i0 + i];
    atomicAdd(&cs[d], s);
}

__global__ void posdot_kernel() {
    float s = 0.f;
    for (int d = threadIdx.x; d < NDIM; d += 256) s += g_csA[d] * g_csB[d];
    for (int off = 16; off; off >>= 1) s += __shfl_xor_sync(0xffffffffu, s, off);
    __shared__ float red[8];
    if ((threadIdx.x & 31) == 0) red[threadIdx.x >> 5] = s;
    __syncthreads();
    if (threadIdx.x == 0) {
        float t = 0.f;
        #pragma unroll
        for (int w = 0; w < 8; w++) t += red[w];
        g_pos = t;
    }
}

// ---------------- pipelined FP8 mma.sync GEMM + exp-sum ----------------
// CTA tile 256(M) x 128(N), BK=64 fp8, 4-stage cp.async pipeline.
// 512 threads = 16 warps (4 in M x 4 in N), warp tile 64x32.
#define BM 256
#define BN 128
#define BK 64
#define STAGES 4
#define AST 80                         // bytes per smem row (64 data + 16 pad)
#define A_BYTES_S (BM * AST)           // 20480
#define B_BYTES_S (BN * AST)           // 10240
#define STAGE_BYTES (A_BYTES_S + B_BYTES_S)  // 30720
#define SMEM_BYTES (STAGES * STAGE_BYTES)    // 122880
#define KTILES (NDIM / BK)             // 32

__device__ __forceinline__ uint32_t cvta_s(const void* p) {
    uint32_t a;
    asm("{ .reg .u64 t; cvta.to.shared.u64 t, %1; cvt.u32.u64 %0, t; }" : "=r"(a) : "l"(p));
    return a;
}
__device__ __forceinline__ void cp16(uint32_t dst, const void* src) {
    asm volatile("cp.async.cg.shared.global [%0], [%1], 16;" :: "r"(dst), "l"(src));
}
__device__ __forceinline__ void ldmatrix_x4(uint32_t r[4], uint32_t addr) {
    asm volatile("ldmatrix.sync.aligned.m8n8.x4.shared.b16 {%0,%1,%2,%3}, [%4];"
                 : "=r"(r[0]), "=r"(r[1]), "=r"(r[2]), "=r"(r[3]) : "r"(addr));
}

__global__ __launch_bounds__(512, 1) void gemm_expsum_kernel() {
    extern __shared__ uint8_t sm[];
    const int tid  = threadIdx.x;
    const int wid  = tid >> 5;
    const int lane = tid & 31;
    const int wm   = (wid & 3) * 64;     // 4 warps in M
    const int wn   = (wid >> 2) * 32;    // 4 warps in N
    const int bm   = blockIdx.y * BM;
    const int bn   = blockIdx.x * BN;

    float acc[16][4];
    #pragma unroll
    for (int i = 0; i < 16; i++)
        #pragma unroll
        for (int j = 0; j < 4; j++) acc[i][j] = 0.f;

    const int lr = tid >> 2;            // 0..127
    const int lc = (tid & 3) * 16;      // 16B chunk within 64B row

    #define LOAD_STAGE(kt, s) do {                                                   \
        uint8_t* sA = sm + (s) * STAGE_BYTES;                                        \
        uint8_t* sB = sA + A_BYTES_S;                                                \
        int k0 = (kt) * BK;                                                          \
        cp16(cvta_s(&sA[lr * AST + lc]),                                             \
             g_A8 + (size_t)(bm + lr) * NDIM + k0 + lc);                             \
        cp16(cvta_s(&sA[(lr + 128) * AST + lc]),                                     \
             g_A8 + (size_t)(bm + lr + 128) * NDIM + k0 + lc);                       \
        cp16(cvta_s(&sB[lr * AST + lc]),                                             \
             g_C8 + (size_t)(bn + lr) * NDIM + k0 + lc);                             \
        asm volatile("cp.async.commit_group;" ::: "memory");                         \
    } while (0)

    #pragma unroll
    for (int s = 0; s < STAGES - 1; s++) LOAD_STAGE(s, s);
    asm volatile("cp.async.wait_group %0;" :: "n"(STAGES - 2) : "memory");
    __syncthreads();

    for (int kt = 0; kt < KTILES; kt++) {
        const int s = kt & (STAGES - 1);
        const int nx = kt + STAGES - 1;
        if (nx < KTILES) LOAD_STAGE(nx, nx & (STAGES - 1));

        uint8_t* sA = sm + s * STAGE_BYTES;
        uint8_t* sB = sA + A_BYTES_S;

        #pragma unroll
        for (int ks = 0; ks < 2; ks++) {
            const int kb = ks * 32;                 // byte offset of k-step (32 fp8)
            uint32_t bfrag[4][2];
            #pragma unroll
            for (int nt = 0; nt < 4; nt += 2) {
                int nrow = wn + nt * 8 + (lane >> 4) * 8 + (lane & 7);
                int colb = kb + ((lane >> 3) & 1) * 16;
                uint32_t r4[4];
                ldmatrix_x4(r4, cvta_s(&sB[nrow * AST + colb]));
                bfrag[nt][0]     = r4[0];
                bfrag[nt][1]     = r4[1];
                bfrag[nt + 1][0] = r4[2];
                bfrag[nt + 1][1] = r4[3];
            }
            #pragma unroll
            for (int mt = 0; mt < 4; mt++) {
                uint32_t af[4];
                int row  = wm + mt * 16 + (lane & 15);
                int colb = kb + (lane >> 4) * 16;
                ldmatrix_x4(af, cvta_s(&sA[row * AST + colb]));
                #pragma unroll
                for (int nt = 0; nt < 4; nt++) {
                    float* c = acc[mt * 4 + nt];
                    asm volatile(
                        "mma.sync.aligned.m16n8k32.row.col.f32.e4m3.e4m3.f32 "
                        "{%0,%1,%2,%3}, {%4,%5,%6,%7}, {%8,%9}, {%0,%1,%2,%3};"
                        : "+f"(c[0]), "+f"(c[1]), "+f"(c[2]), "+f"(c[3])
                        : "r"(af[0]), "r"(af[1]), "r"(af[2]), "r"(af[3]),
                          "r"(bfrag[nt][0]), "r"(bfrag[nt][1]));
                }
            }
        }
        asm volatile("cp.async.wait_group %0;" :: "n"(STAGES - 2) : "memory");
        __syncthreads();
    }

    // epilogue: sum exp(2*sim) ; acc = sim * QSCALE^2 -> scale back
    float local = 0.f;
    #pragma unroll
    for (int i = 0; i < 16; i++)
        #pragma unroll
        for (int j = 0; j < 4; j++)
            local += __expf(acc[i][j] * (TEMP_INV * QS2_INV));

    for (int off = 16; off; off >>= 1) local += __shfl_xor_sync(0xffffffffu, local, off);
    __shared__ float red[16];
    if (lane == 0) red[wid] = local;
    __syncthreads();
    if (tid == 0) {
        float t = 0.f;
        #pragma unroll
        for (int w = 0; w < 16; w++) t += red[w];
        atomicAdd(&g_S, (double)t);
    }
}

// ---------------- final scalar ----------------
__global__ void final_kernel(float* __restrict__ out) {
    double n2 = (double)NROWS * (double)NROWS;
    double loss = log(g_S) - (double)g_pos * (double)TEMP_INV / n2;
    out[0] = (float)loss;
}

// ---------------- host ----------------
extern "C" void kernel_launch(void* const* d_in, const int* in_sizes, int n_in,
                              void* d_out, int out_size) {
    const float* xA = (const float*)d_in[0];  // x_source
    const float* xB = (const float*)d_in[1];  // x_bc_target
    const float* xC = (const float*)d_in[2];  // x_raw_target
    float* out = (float*)d_out;

    zero_kernel<<<8, 256>>>();

    fuse_norm_kernel<<<NROWS, 256>>>(xA, g_A8);
    fuse_norm_kernel<<<NROWS, 256>>>(xC, g_C8);
    row_norms_kernel<<<NROWS, 256>>>(xB, g_invB);

    {
        dim3 gridp(NDIM / 2 / 256, 32);
        colsum_fp8_kernel<<<gridp, 256>>>(g_A8, g_csA);
        dim3 grid(NDIM / 256, 32);
        colsum_f32_kernel<<<grid, 256>>>(xB, g_invB, g_csB);
    }
    posdot_kernel<<<1, 256>>>();

    cudaFuncSetAttribute(gemm_expsum_kernel,
                         cudaFuncAttributeMaxDynamicSharedMemorySize, SMEM_BYTES);
    {
        dim3 grid(NROWS / BN, NROWS / BM);
        gemm_expsum_kernel<<<grid, 512, SMEM_BYTES>>>();
    }

    final_kernel<<<1, 1>>>(out);
}

// round 10
// speedup vs baseline: 1.1465x; 1.1465x over previous
#include <cuda_runtime.h>
#include <cuda_fp16.h>
#include <math.h>
#include <stdint.h>

#define NROWS 4096
#define NDIM  2048
#define TEMP_INV 2.0f
#define QSCALE 64.0f           // fp8 quantization scale
#define QS2_INV (1.0f / (QSCALE * QSCALE))

// ---------------- device scratch ----------------
__device__ __align__(1024) uint8_t g_A8[NROWS * NDIM];   // e4m3, normalized * 64
__device__ __align__(1024) uint8_t g_C8[NROWS * NDIM];   // e4m3, normalized * 64
__device__ float  g_invB[NROWS];
__device__ float  g_csA[NDIM];
__device__ float  g_csB[NDIM];
__device__ double g_S;
__device__ float  g_pos;

// ---------------- raw-PTX fp8 conversion ----------------
__device__ __forceinline__ uint16_t pack_e4m3x2(float hi, float lo) {
    uint16_t r;
    asm("cvt.rn.satfinite.e4m3x2.f32 %0, %1, %2;" : "=h"(r) : "f"(hi), "f"(lo));
    return r;
}
__device__ __forceinline__ float2 unpack_e4m3x2(uint16_t v) {
    uint32_t h2;
    asm("cvt.rn.f16x2.e4m3x2 %0, %1;" : "=r"(h2) : "h"(v));
    __half2 h = *reinterpret_cast<__half2*>(&h2);
    return __half22float2(h);
}

// ---------------- zero accumulators ----------------
__global__ void zero_kernel() {
    int i = blockIdx.x * blockDim.x + threadIdx.x;
    if (i < NDIM) { g_csA[i] = 0.f; g_csB[i] = 0.f; }
    if (i == 0)   { g_S = 0.0; g_pos = 0.f; }
}

// ---------------- fused norm + normalize -> e4m3 (*64) ----------------
__global__ __launch_bounds__(256) void fuse_norm_kernel(const float* __restrict__ X,
                                                        uint8_t* __restrict__ out) {
    int row = blockIdx.x;
    int tid = threadIdx.x;
    const float4* p = reinterpret_cast<const float4*>(X + (size_t)row * NDIM);
    float4 a = p[tid * 2 + 0];
    float4 b = p[tid * 2 + 1];
    float s = a.x * a.x + a.y * a.y + a.z * a.z + a.w * a.w
            + b.x * b.x + b.y * b.y + b.z * b.z + b.w * b.w;
    for (int off = 16; off; off >>= 1) s += __shfl_xor_sync(0xffffffffu, s, off);
    __shared__ float red[8];
    __shared__ float s_inv;
    if ((tid & 31) == 0) red[tid >> 5] = s;
    __syncthreads();
    if (tid == 0) {
        float t = 0.f;
        #pragma unroll
        for (int w = 0; w < 8; w++) t += red[w];
        s_inv = rsqrtf(t) * QSCALE;
    }
    __syncthreads();
    float inv = s_inv;

    uint16_t q0 = pack_e4m3x2(a.y * inv, a.x * inv);
    uint16_t q1 = pack_e4m3x2(a.w * inv, a.z * inv);
    uint16_t q2 = pack_e4m3x2(b.y * inv, b.x * inv);
    uint16_t q3 = pack_e4m3x2(b.w * inv, b.z * inv);
    uint2 o;
    o.x = (uint32_t)q0 | ((uint32_t)q1 << 16);
    o.y = (uint32_t)q2 | ((uint32_t)q3 << 16);
    reinterpret_cast<uint2*>(out + (size_t)row * NDIM)[tid] = o;
}

// ---------------- per-row inverse L2 norm (B only) ----------------
__global__ void row_norms_kernel(const float* __restrict__ X, float* __restrict__ inv) {
    int row = blockIdx.x;
    const float4* p = reinterpret_cast<const float4*>(X + (size_t)row * NDIM);
    float s = 0.f;
    for (int i = threadIdx.x; i < NDIM / 4; i += blockDim.x) {
        float4 v = p[i];
        s += v.x * v.x + v.y * v.y + v.z * v.z + v.w * v.w;
    }
    for (int off = 16; off; off >>= 1) s += __shfl_xor_sync(0xffffffffu, s, off);
    __shared__ float red[8];
    if ((threadIdx.x & 31) == 0) red[threadIdx.x >> 5] = s;
    __syncthreads();
    if (threadIdx.x == 0) {
        float t = 0.f;
        #pragma unroll
        for (int w = 0; w < 8; w++) t += red[w];
        inv[row] = rsqrtf(t);
    }
}

// ---------------- column sums ----------------
__global__ void colsum_fp8_kernel(const uint8_t* __restrict__ X8,
                                  float* __restrict__ cs) {
    int d2 = blockIdx.x * blockDim.x + threadIdx.x;   // pair index
    int i0 = blockIdx.y * (NROWS / 32);
    float s0 = 0.f, s1 = 0.f;
    #pragma unroll 4
    for (int i = 0; i < NROWS / 32; i++) {
        uint16_t v = *reinterpret_cast<const uint16_t*>(&X8[(size_t)(i0 + i) * NDIM + d2 * 2]);
        float2 f = unpack_e4m3x2(v);
        s0 += f.x; s1 += f.y;
    }
    atomicAdd(&cs[d2 * 2 + 0], s0 * (1.0f / QSCALE));
    atomicAdd(&cs[d2 * 2 + 1], s1 * (1.0f / QSCALE));
}

__global__ void colsum_f32_kernel(const float* __restrict__ X,
                                  const float* __restrict__ inv,
                                  float* __restrict__ cs) {
    int d  = blockIdx.x * blockDim.x + threadIdx.x;
    int i0 = blockIdx.y * (NROWS / 32);
    float s = 0.f;
    #pragma unroll 4
    for (int i = 0; i < NROWS / 32; i++)
        s += X[(size_t)(i0 + i) * NDIM + d] * inv[i0 + i];
    atomicAdd(&cs[d], s);
}

__global__ void posdot_kernel() {
    float s = 0.f;
    for (int d = threadIdx.x; d < NDIM; d += 256) s += g_csA[d] * g_csB[d];
    for (int off = 16; off; off >>= 1) s += __shfl_xor_sync(0xffffffffu, s, off);
    __shared__ float red[8];
    if ((threadIdx.x & 31) == 0) red[threadIdx.x >> 5] = s;
    __syncthreads();
    if (threadIdx.x == 0) {
        float t = 0.f;
        #pragma unroll
        for (int w = 0; w < 8; w++) t += red[w];
        g_pos = t;
    }
}

// ---------------- pipelined FP8 mma.sync GEMM + exp-sum ----------------
// CTA tile 128(M) x 128(N), BK=64 fp8, 4-stage cp.async pipeline.
// 256 threads = 8 warps (2 in M x 4 in N), warp tile 64x32.
// 80 KB smem -> 2 CTAs/SM for cross-CTA latency overlap.
#define BM 128
#define BN 128
#define BK 64
#define STAGES 4
#define AST 80                         // bytes per smem row (64 data + 16 pad)
#define A_BYTES_S (BM * AST)           // 10240
#define B_BYTES_S (BN * AST)           // 10240
#define STAGE_BYTES (A_BYTES_S + B_BYTES_S)  // 20480
#define SMEM_BYTES (STAGES * STAGE_BYTES)    // 81920
#define KTILES (NDIM / BK)             // 32

__device__ __forceinline__ uint32_t cvta_s(const void* p) {
    uint32_t a;
    asm("{ .reg .u64 t; cvta.to.shared.u64 t, %1; cvt.u32.u64 %0, t; }" : "=r"(a) : "l"(p));
    return a;
}
__device__ __forceinline__ void cp16(uint32_t dst, const void* src) {
    asm volatile("cp.async.cg.shared.global [%0], [%1], 16;" :: "r"(dst), "l"(src));
}
__device__ __forceinline__ void ldmatrix_x4(uint32_t r[4], uint32_t addr) {
    asm volatile("ldmatrix.sync.aligned.m8n8.x4.shared.b16 {%0,%1,%2,%3}, [%4];"
                 : "=r"(r[0]), "=r"(r[1]), "=r"(r[2]), "=r"(r[3]) : "r"(addr));
}

__global__ __launch_bounds__(256, 2) void gemm_expsum_kernel() {
    extern __shared__ uint8_t sm[];
    const int tid  = threadIdx.x;
    const int wid  = tid >> 5;
    const int lane = tid & 31;
    const int wm   = (wid & 1) * 64;     // 2 warps in M
    const int wn   = (wid >> 1) * 32;    // 4 warps in N
    const int bm   = blockIdx.y * BM;
    const int bn   = blockIdx.x * BN;

    float acc[16][4];
    #pragma unroll
    for (int i = 0; i < 16; i++)
        #pragma unroll
        for (int j = 0; j < 4; j++) acc[i][j] = 0.f;

    const int lr = tid >> 2;            // 0..63
    const int lc = (tid & 3) * 16;      // 16B chunk within 64B row

    #define LOAD_STAGE(kt, s) do {                                                   \
        uint8_t* sA = sm + (s) * STAGE_BYTES;                                        \
        uint8_t* sB = sA + A_BYTES_S;                                                \
        int k0 = (kt) * BK;                                                          \
        cp16(cvta_s(&sA[lr * AST + lc]),                                             \
             g_A8 + (size_t)(bm + lr) * NDIM + k0 + lc);                             \
        cp16(cvta_s(&sA[(lr + 64) * AST + lc]),                                      \
             g_A8 + (size_t)(bm + lr + 64) * NDIM + k0 + lc);                        \
        cp16(cvta_s(&sB[lr * AST + lc]),                                             \
             g_C8 + (size_t)(bn + lr) * NDIM + k0 + lc);                             \
        cp16(cvta_s(&sB[(lr + 64) * AST + lc]),                                      \
             g_C8 + (size_t)(bn + lr + 64) * NDIM + k0 + lc);                        \
        asm volatile("cp.async.commit_group;" ::: "memory");                         \
    } while (0)

    #pragma unroll
    for (int s = 0; s < STAGES - 1; s++) LOAD_STAGE(s, s);
    asm volatile("cp.async.wait_group %0;" :: "n"(STAGES - 2) : "memory");
    __syncthreads();

    for (int kt = 0; kt < KTILES; kt++) {
        const int s = kt & (STAGES - 1);
        const int nx = kt + STAGES - 1;
        if (nx < KTILES) LOAD_STAGE(nx, nx & (STAGES - 1));

        uint8_t* sA = sm + s * STAGE_BYTES;
        uint8_t* sB = sA + A_BYTES_S;

        #pragma unroll
        for (int ks = 0; ks < 2; ks++) {
            const int kb = ks * 32;                 // byte offset of k-step (32 fp8)
            uint32_t bfrag[4][2];
            #pragma unroll
            for (int nt = 0; nt < 4; nt += 2) {
                int nrow = wn + nt * 8 + (lane >> 4) * 8 + (lane & 7);
                int colb = kb + ((lane >> 3) & 1) * 16;
                uint32_t r4[4];
                ldmatrix_x4(r4, cvta_s(&sB[nrow * AST + colb]));
                bfrag[nt][0]     = r4[0];
                bfrag[nt][1]     = r4[1];
                bfrag[nt + 1][0] = r4[2];
                bfrag[nt + 1][1] = r4[3];
            }
            #pragma unroll
            for (int mt = 0; mt < 4; mt++) {
                uint32_t af[4];
                int row  = wm + mt * 16 + (lane & 15);
                int colb = kb + (lane >> 4) * 16;
                ldmatrix_x4(af, cvta_s(&sA[row * AST + colb]));
                #pragma unroll
                for (int nt = 0; nt < 4; nt++) {
                    float* c = acc[mt * 4 + nt];
                    asm volatile(
                        "mma.sync.aligned.m16n8k32.row.col.f32.e4m3.e4m3.f32 "
                        "{%0,%1,%2,%3}, {%4,%5,%6,%7}, {%8,%9}, {%0,%1,%2,%3};"
                        : "+f"(c[0]), "+f"(c[1]), "+f"(c[2]), "+f"(c[3])
                        : "r"(af[0]), "r"(af[1]), "r"(af[2]), "r"(af[3]),
                          "r"(bfrag[nt][0]), "r"(bfrag[nt][1]));
                }
            }
        }
        asm volatile("cp.async.wait_group %0;" :: "n"(STAGES - 2) : "memory");
        __syncthreads();
    }

    // epilogue: sum exp(2*sim) ; acc = sim * QSCALE^2 -> scale back
    float local = 0.f;
    #pragma unroll
    for (int i = 0; i < 16; i++)
        #pragma unroll
        for (int j = 0; j < 4; j++)
            local += __expf(acc[i][j] * (TEMP_INV * QS2_INV));

    for (int off = 16; off; off >>= 1) local += __shfl_xor_sync(0xffffffffu, local, off);
    __shared__ float red[8];
    if (lane == 0) red[wid] = local;
    __syncthreads();
    if (tid == 0) {
        float t = 0.f;
        #pragma unroll
        for (int w = 0; w < 8; w++) t += red[w];
        atomicAdd(&g_S, (double)t);
    }
}

// ---------------- final scalar ----------------
__global__ void final_kernel(float* __restrict__ out) {
    double n2 = (double)NROWS * (double)NROWS;
    double loss = log(g_S) - (double)g_pos * (double)TEMP_INV / n2;
    out[0] = (float)loss;
}

// ---------------- host ----------------
extern "C" void kernel_launch(void* const* d_in, const int* in_sizes, int n_in,
                              void* d_out, int out_size) {
    const float* xA = (const float*)d_in[0];  // x_source
    const float* xB = (const float*)d_in[1];  // x_bc_target
    const float* xC = (const float*)d_in[2];  // x_raw_target
    float* out = (float*)d_out;

    // Order chosen so the GEMM is the 4th launch (ncu -s 5 with ~2 harness
    // launches prepended lands on it). All dependencies are stream-ordered.
    fuse_norm_kernel<<<NROWS, 256>>>(xA, g_A8);
    fuse_norm_kernel<<<NROWS, 256>>>(xC, g_C8);
    zero_kernel<<<8, 256>>>();

    cudaFuncSetAttribute(gemm_expsum_kernel,
                         cudaFuncAttributeMaxDynamicSharedMemorySize, SMEM_BYTES);
    {
        dim3 grid(NROWS / BN, NROWS / BM);
        gemm_expsum_kernel<<<grid, 256, SMEM_BYTES>>>();
    }

    row_norms_kernel<<<NROWS, 256>>>(xB, g_invB);
    {
        dim3 gridp(NDIM / 2 / 256, 32);
        colsum_fp8_kernel<<<gridp, 256>>>(g_A8, g_csA);
        dim3 grid(NDIM / 256, 32);
        colsum_f32_kernel<<<grid, 256>>>(xB, g_invB, g_csB);
    }
    posdot_kernel<<<1, 256>>>();

    final_kernel<<<1, 1>>>(out);
}